// round 7
// baseline (speedup 1.0000x reference)
#include <cuda_runtime.h>

// Problem constants
#define N_ROWS   16384
#define IN_DIM   64
#define NEXP     256
#define CAP      128     // per-expert bucket capacity (binomial max ~90, 8-sigma margin)
#define TM       64      // rows per tile
#define TILES_Y  (CAP / TM)
#define THREADS  512

typedef unsigned long long ULL;

// ---------------- scratch (no allocations allowed) ----------------
__device__ int g_cnt[NEXP];
__device__ int g_bucket[NEXP * CAP];

// ---------------- small helpers ----------------
__device__ __forceinline__ void fma2(ULL &acc, ULL a, ULL b) {
    asm("fma.rn.f32x2 %0, %1, %2, %0;" : "+l"(acc) : "l"(a), "l"(b));
}
__device__ __forceinline__ ULL dup2(float x) {
    ULL r; asm("mov.b64 %0, {%1, %1};" : "=l"(r) : "f"(x)); return r;
}
__device__ __forceinline__ float2 unpack2(ULL v) {
    float2 r;
    r.x = __uint_as_float((unsigned)(v & 0xFFFFFFFFull));
    r.y = __uint_as_float((unsigned)(v >> 32));
    return r;
}
// tanh(x) = sign(x) * (1 - t)/(1 + t), t = exp(-2|x|)
__device__ __forceinline__ float fast_tanh(float x) {
    float ax = fabsf(x);
    float t = __expf(-2.0f * ax);
    float r = __fdividef(1.0f - t, 1.0f + t);
    return copysignf(r, x);
}

// ---------------- grouping: single bucket-fill kernel ----------------
__global__ void k_fill(const int* __restrict__ ind) {
    int i = blockIdx.x * blockDim.x + threadIdx.x;
    int e = ind[i];
    int p = atomicAdd(&g_cnt[e], 1);
    if (p < CAP) g_bucket[e * CAP + p] = i;
}

// ---------------- GEMM microkernel ----------------
// Warp tile: 8 rows x 128 cols. xp: pre-offset to warp's first row.
// wp: pre-offset to warp's column offset (stride 256 floats per k-row).
// Per k-quad: 4 weight ulonglong2 held; rows processed in pairs (register cap).
template <int KK, int LDX>
__device__ __forceinline__ void gemmc(const float* __restrict__ xp,
                                      const float* __restrict__ wp,
                                      ULL acc[8][2]) {
    #pragma unroll 2
    for (int k = 0; k < KK; k += 4) {
        ulonglong2 w[4];
        #pragma unroll
        for (int kk = 0; kk < 4; kk++)
            w[kk] = *(const ulonglong2*)&wp[(k + kk) * 256];
        #pragma unroll
        for (int p = 0; p < 4; p++) {
            float4 x0 = *(const float4*)&xp[(2 * p) * LDX + k];
            float4 x1 = *(const float4*)&xp[(2 * p + 1) * LDX + k];
            #pragma unroll
            for (int kk = 0; kk < 4; kk++) {
                float a0 = (kk == 0) ? x0.x : (kk == 1) ? x0.y : (kk == 2) ? x0.z : x0.w;
                float a1 = (kk == 0) ? x1.x : (kk == 1) ? x1.y : (kk == 2) ? x1.z : x1.w;
                ULL d0 = dup2(a0), d1 = dup2(a1);
                fma2(acc[2 * p][0], d0, w[kk].x);
                fma2(acc[2 * p][1], d0, w[kk].y);
                fma2(acc[2 * p + 1][0], d1, w[kk].x);
                fma2(acc[2 * p + 1][1], d1, w[kk].y);
            }
        }
    }
}

// smem (floats): sA [64][256] h1/h2 | sB x[64][64] then W3 [256][64] | sC W1 [64][256] / W2 dbuf 2x[32][256]
#define SMEM_FLOATS (3 * 16384)   // 192 KB

__global__ __launch_bounds__(THREADS, 1)
void k_mlp(const float* __restrict__ Xg,
           const float* __restrict__ W1, const float* __restrict__ B1,
           const float* __restrict__ W2, const float* __restrict__ B2,
           const float* __restrict__ W3, const float* __restrict__ B3,
           float* __restrict__ Og) {
    int e = blockIdx.x;
    int cnt = min(g_cnt[e], CAP);
    int rs = (int)blockIdx.y * TM;
    if (rs >= cnt) return;
    int mrows = min(TM, cnt - rs);

    extern __shared__ float sm[];
    float* sA = sm;              // h1 / h2
    float* sB = sm + 16384;      // x, then W3 [k][64]
    float* sC = sm + 32768;      // W1 [k][256] / W2 double buffer

    int tid = threadIdx.x;
    int og = tid & 31;
    int wid = tid >> 5;
    int rg = wid & 7;                 // row group: rows rg*8 .. +8
    int cg = wid >> 3;                // column half
    int cgo = cg * 128 + og * 4;      // thread's column offset
    bool wact = (rg * 8 < mrows);

    // ---- stage x rows into sB[64][64] (zero-pad) ----
    {
        int m = tid >> 3;             // 0..63
        int part = tid & 7;
        float4 v0, v1;
        if (m < mrows) {
            int n = g_bucket[e * CAP + rs + m];
            const float4* src = (const float4*)(Xg + (size_t)n * IN_DIM) + part * 2;
            v0 = src[0]; v1 = src[1];
        } else {
            v0 = make_float4(0.f, 0.f, 0.f, 0.f);
            v1 = v0;
        }
        float4* dst = (float4*)sB + tid * 2;
        dst[0] = v0; dst[1] = v1;
    }
    // ---- stage W1 transposed into sC[k][256] ----
    {
        int o = tid & 255;
        int kh = tid >> 8;            // 0/1: half of k range
        const float* wsrc = W1 + ((size_t)e * 256 + o) * 64 + kh * 32;
        #pragma unroll
        for (int j = 0; j < 8; j++) {
            float4 v = *(const float4*)(wsrc + j * 4);
            int k = kh * 32 + j * 4;
            sC[(k + 0) * 256 + o] = v.x;
            sC[(k + 1) * 256 + o] = v.y;
            sC[(k + 2) * 256 + o] = v.z;
            sC[(k + 3) * 256 + o] = v.w;
        }
    }
    __syncthreads();

    ULL acc[8][2];
    int o2 = tid & 255;               // W2 staging: output row
    int kh2 = (tid >> 8) * 16;        // W2 staging: k sub-offset within chunk
    const float* w2base = W2 + ((size_t)e * 256 + o2) * 256 + kh2;
    int o3 = tid & 63;                // W3 staging: output column
    int g3 = (tid >> 6) * 4;          // W3 staging: 4-k slice within chunk
    const float* w3src = W3 + ((size_t)e * 64 + o3) * 256 + g3;
    float4 pf[4];

    // ---- layer 1: 64 -> 256, tanh -> sA ----
    {
        ulonglong2 bv = *(const ulonglong2*)(B1 + (size_t)e * 256 + cgo);
        #pragma unroll
        for (int i = 0; i < 8; i++) { acc[i][0] = bv.x; acc[i][1] = bv.y; }
        if (wact) gemmc<64, 64>(sB + rg * 8 * 64, sC + cgo, acc);

        // prefetch W2 chunk 0
        #pragma unroll
        for (int j = 0; j < 4; j++)
            pf[j] = *(const float4*)(w2base + j * 4);

        if (wact) {
            #pragma unroll
            for (int i = 0; i < 8; i++) {
                float2 p0 = unpack2(acc[i][0]), p1 = unpack2(acc[i][1]);
                float4 a = make_float4(fast_tanh(p0.x), fast_tanh(p0.y),
                                       fast_tanh(p1.x), fast_tanh(p1.y));
                *(float4*)&sA[(rg * 8 + i) * 256 + cgo] = a;
            }
        }
    }
    __syncthreads();   // layer-1 reads of sB/sC done

    // STS W2 chunk 0 -> buffer 0
    #pragma unroll
    for (int j = 0; j < 4; j++) {
        int k = kh2 + j * 4;
        sC[(k + 0) * 256 + o2] = pf[j].x;
        sC[(k + 1) * 256 + o2] = pf[j].y;
        sC[(k + 2) * 256 + o2] = pf[j].z;
        sC[(k + 3) * 256 + o2] = pf[j].w;
    }
    __syncthreads();

    // ---- layer 2: 256 -> 256, 8 pipelined chunks of 32 k-rows ----
    {
        ulonglong2 bv = *(const ulonglong2*)(B2 + (size_t)e * 256 + cgo);
        #pragma unroll
        for (int i = 0; i < 8; i++) { acc[i][0] = bv.x; acc[i][1] = bv.y; }

        #pragma unroll 1
        for (int c = 0; c < 8; c++) {
            const float* cur = sC + (c & 1) * 8192;
            float* nxt = sC + ((c + 1) & 1) * 8192;

            if (c < 7) {
                #pragma unroll
                for (int j = 0; j < 4; j++)
                    pf[j] = *(const float4*)(w2base + (c + 1) * 32 + j * 4);
            }
            // W3 slice for this chunk (k = c*32 + g3 .. +4); x region dead after layer 1
            float4 w3v = *(const float4*)(w3src + c * 32);

            if (wact)
                gemmc<32, 256>(sA + rg * 8 * 256 + c * 32, cur + cgo, acc);

            {
                int kb = c * 32 + g3;
                sB[(kb + 0) * 64 + o3] = w3v.x;
                sB[(kb + 1) * 64 + o3] = w3v.y;
                sB[(kb + 2) * 64 + o3] = w3v.z;
                sB[(kb + 3) * 64 + o3] = w3v.w;
            }
            if (c < 7) {
                #pragma unroll
                for (int j = 0; j < 4; j++) {
                    int k = kh2 + j * 4;
                    nxt[(k + 0) * 256 + o2] = pf[j].x;
                    nxt[(k + 1) * 256 + o2] = pf[j].y;
                    nxt[(k + 2) * 256 + o2] = pf[j].z;
                    nxt[(k + 3) * 256 + o2] = pf[j].w;
                }
            }
            __syncthreads();
        }

        // tanh -> h2 in-place into sA (own rows/col-half only)
        if (wact) {
            #pragma unroll
            for (int i = 0; i < 8; i++) {
                float2 p0 = unpack2(acc[i][0]), p1 = unpack2(acc[i][1]);
                float4 a = make_float4(fast_tanh(p0.x), fast_tanh(p0.y),
                                       fast_tanh(p1.x), fast_tanh(p1.y));
                *(float4*)&sA[(rg * 8 + i) * 256 + cgo] = a;
            }
        }
    }
    __syncthreads();

    // ---- layer 3: 256 -> 64, linear, scatter to output ----
    // 16 warps: warp wid handles rows wid*4 .. +4, all 64 outputs
    if (wid * 4 < mrows) {
        ULL acc3[4];
        ULL b3 = *(const ULL*)(B3 + (size_t)e * 64 + og * 2);
        #pragma unroll
        for (int i = 0; i < 4; i++) acc3[i] = b3;

        #pragma unroll 2
        for (int k = 0; k < 256; k += 4) {
            float4 xr[4];
            #pragma unroll
            for (int i = 0; i < 4; i++)
                xr[i] = *(const float4*)&sA[(wid * 4 + i) * 256 + k];
            #pragma unroll
            for (int kk = 0; kk < 4; kk++) {
                ULL w = *(const ULL*)&sB[(k + kk) * 64 + og * 2];
                #pragma unroll
                for (int i = 0; i < 4; i++) {
                    float xv = (kk == 0) ? xr[i].x : (kk == 1) ? xr[i].y
                             : (kk == 2) ? xr[i].z : xr[i].w;
                    fma2(acc3[i], dup2(xv), w);
                }
            }
        }
        #pragma unroll
        for (int i = 0; i < 4; i++) {
            int m = wid * 4 + i;
            if (m < mrows) {
                int n = g_bucket[e * CAP + rs + m];
                *(ULL*)&Og[(size_t)n * 64 + og * 2] = acc3[i];
            }
        }
    }
}

// ---------------- launch ----------------
extern "C" void kernel_launch(void* const* d_in, const int* in_sizes, int n_in,
                              void* d_out, int out_size) {
    const float* x  = (const float*)d_in[0];
    const int*   ind = (const int*)d_in[1];
    const float* W1 = (const float*)d_in[2];
    const float* b1 = (const float*)d_in[3];
    const float* W2 = (const float*)d_in[4];
    const float* b2 = (const float*)d_in[5];
    const float* Wl = (const float*)d_in[6];
    const float* bl = (const float*)d_in[7];
    float* out = (float*)d_out;

    (void)in_sizes; (void)n_in; (void)out_size;

    cudaFuncSetAttribute(k_mlp, cudaFuncAttributeMaxDynamicSharedMemorySize,
                         SMEM_FLOATS * (int)sizeof(float));

    void* cnt_ptr = nullptr;
    cudaGetSymbolAddress(&cnt_ptr, g_cnt);
    cudaMemsetAsync(cnt_ptr, 0, NEXP * sizeof(int));

    k_fill<<<N_ROWS / 256, 256>>>(ind);
    k_mlp<<<dim3(NEXP, TILES_Y), THREADS, SMEM_FLOATS * sizeof(float)>>>(
        x, W1, b1, W2, b2, Wl, bl, out);
}

// round 8
// speedup vs baseline: 1.0383x; 1.0383x over previous
#include <cuda_runtime.h>

// Problem constants
#define N_ROWS   16384
#define IN_DIM   64
#define NEXP     256
#define CAP      128     // per-expert bucket capacity (binomial max ~90, 8-sigma margin)
#define TM       32      // rows per tile
#define TILES_Y  (CAP / TM)
#define THREADS  256

typedef unsigned long long ULL;

// ---------------- scratch (no allocations allowed) ----------------
__device__ int g_cnt[NEXP];
__device__ int g_bucket[NEXP * CAP];

// ---------------- small helpers ----------------
__device__ __forceinline__ void fma2(ULL &acc, ULL a, ULL b) {
    asm("fma.rn.f32x2 %0, %1, %2, %0;" : "+l"(acc) : "l"(a), "l"(b));
}
__device__ __forceinline__ ULL dup2(float x) {
    ULL r; asm("mov.b64 %0, {%1, %1};" : "=l"(r) : "f"(x)); return r;
}
__device__ __forceinline__ float2 unpack2(ULL v) {
    float2 r;
    r.x = __uint_as_float((unsigned)(v & 0xFFFFFFFFull));
    r.y = __uint_as_float((unsigned)(v >> 32));
    return r;
}
// tanh(x) = sign(x) * (1 - t)/(1 + t), t = exp(-2|x|)
__device__ __forceinline__ float fast_tanh(float x) {
    float ax = fabsf(x);
    float t = __expf(-2.0f * ax);
    float r = __fdividef(1.0f - t, 1.0f + t);
    return copysignf(r, x);
}

// ---------------- grouping ----------------
__global__ void k_fill(const int* __restrict__ ind) {
    int i = blockIdx.x * blockDim.x + threadIdx.x;
    int e = ind[i];
    int p = atomicAdd(&g_cnt[e], 1);
    if (p < CAP) g_bucket[e * CAP + p] = i;
}

// ---------------- GEMM microkernel (16 k-steps) ----------------
// Thread tile: 8 outputs (o0..o0+8, as 4 f32x2 pairs) x 4 rows (m0..m0+4).
// xb: activation base pre-offset to row m0 (row stride LDX, cols XOR-swizzled by swzv).
// wb: weight chunk buffer pre-offset to o0 (row stride 256).
// kx: global x-column base of this chunk.
template <int LDX>
__device__ __forceinline__ void gemm16(const float* __restrict__ xb,
                                       const float* __restrict__ wb,
                                       int kx, int swzv, ULL acc[4][4]) {
    #pragma unroll
    for (int q = 0; q < 4; q++) {
        float4 xr[4];
        int xc = (kx + q * 4) ^ swzv;
        #pragma unroll
        for (int i = 0; i < 4; i++)
            xr[i] = *(const float4*)&xb[i * LDX + xc];
        #pragma unroll
        for (int kk = 0; kk < 4; kk++) {
            ulonglong2 wlo = *(const ulonglong2*)&wb[(q * 4 + kk) * 256];
            ulonglong2 whi = *(const ulonglong2*)&wb[(q * 4 + kk) * 256 + 4];
            #pragma unroll
            for (int i = 0; i < 4; i++) {
                float xv = (kk == 0) ? xr[i].x : (kk == 1) ? xr[i].y
                         : (kk == 2) ? xr[i].z : xr[i].w;
                ULL d = dup2(xv);
                fma2(acc[0][i], d, wlo.x);
                fma2(acc[1][i], d, wlo.y);
                fma2(acc[2][i], d, whi.x);
                fma2(acc[3][i], d, whi.y);
            }
        }
    }
}

// smem (floats): sA [32][256] h1/h2 (8192) | sX [32][64] x (2048) | sW 2 x [16][256] (8192)
#define SMEM_FLOATS (8192 + 2048 + 8192)   // 18432 floats = 72 KB

__global__ __launch_bounds__(THREADS, 2)
void k_mlp(const float* __restrict__ Xg,
           const float* __restrict__ W1, const float* __restrict__ B1,
           const float* __restrict__ W2, const float* __restrict__ B2,
           const float* __restrict__ W3, const float* __restrict__ B3,
           float* __restrict__ Og) {
    int e = blockIdx.x;
    int cnt = min(g_cnt[e], CAP);
    int rs = (int)blockIdx.y * TM;
    if (rs >= cnt) return;
    int mrows = min(TM, cnt - rs);

    extern __shared__ float sm[];
    float* sA = sm;                 // h1 then h2 (in place)
    float* sX = sm + 8192;          // x
    float* sW = sm + 8192 + 2048;   // 2 weight buffers of 4096 floats

    int tid = threadIdx.x;
    int lane = tid & 31;
    int wid = tid >> 5;
    int c = lane & 7, r = lane >> 3;     // col/row position within warp
    int cb = wid & 3, rb = wid >> 2;     // warp col-block / row-block
    int o0 = cb * 64 + c * 8;            // 8 outputs
    int m0 = rb * 16 + r * 4;            // 4 rows
    int swzv = ((m0 >> 2) & 7) * 4;      // per-thread row-quad swizzle

    // ---- stage x into sX[m][64] (cols XOR-swizzled), zero-pad m >= mrows ----
    {
        int mx = tid >> 3, px = tid & 7;
        float4 v0, v1;
        if (mx < mrows) {
            int n = g_bucket[e * CAP + rs + mx];
            const float4* src = (const float4*)(Xg + (size_t)n * IN_DIM) + px * 2;
            v0 = src[0]; v1 = src[1];
        } else {
            v0 = make_float4(0.f, 0.f, 0.f, 0.f);
            v1 = v0;
        }
        int swzx = ((mx >> 2) & 7) * 4;
        *(float4*)&sX[mx * 64 + ((px * 8) ^ swzx)] = v0;
        *(float4*)&sX[mx * 64 + ((px * 8 + 4) ^ swzx)] = v1;
    }
    // ---- stage W1 chunk 0 -> buf0 ----
    const float* w1base = W1 + ((size_t)e * 256 + tid) * 64;
    const float* w2base = W2 + ((size_t)e * 256 + tid) * 256;
    {
        #pragma unroll
        for (int j = 0; j < 4; j++) {
            float4 v = *(const float4*)(w1base + j * 4);
            int k = j * 4;
            sW[(k + 0) * 256 + tid] = v.x;
            sW[(k + 1) * 256 + tid] = v.y;
            sW[(k + 2) * 256 + tid] = v.z;
            sW[(k + 3) * 256 + tid] = v.w;
        }
    }
    __syncthreads();

    ULL acc[4][4];
    float4 pf[4];

    // ---- layer 1: 64 -> 256 (4 chunks of 16 k), tanh -> sA ----
    {
        ulonglong2 ba = *(const ulonglong2*)(B1 + (size_t)e * 256 + o0);
        ulonglong2 bb = *(const ulonglong2*)(B1 + (size_t)e * 256 + o0 + 4);
        #pragma unroll
        for (int i = 0; i < 4; i++) {
            acc[0][i] = ba.x; acc[1][i] = ba.y; acc[2][i] = bb.x; acc[3][i] = bb.y;
        }
        #pragma unroll 1
        for (int ck = 0; ck < 4; ck++) {
            const float* nsrc = (ck < 3) ? (w1base + (ck + 1) * 16) : w2base;
            #pragma unroll
            for (int j = 0; j < 4; j++)
                pf[j] = *(const float4*)(nsrc + j * 4);

            gemm16<64>(sX + m0 * 64, sW + (ck & 1) * 4096 + o0, ck * 16, swzv, acc);

            if (ck == 3) {
                // tanh epilogue -> sA[m][256] swizzled
                #pragma unroll
                for (int i = 0; i < 4; i++) {
                    float2 p0 = unpack2(acc[0][i]), p1 = unpack2(acc[1][i]);
                    float2 p2 = unpack2(acc[2][i]), p3 = unpack2(acc[3][i]);
                    float4 a = make_float4(fast_tanh(p0.x), fast_tanh(p0.y),
                                           fast_tanh(p1.x), fast_tanh(p1.y));
                    float4 b = make_float4(fast_tanh(p2.x), fast_tanh(p2.y),
                                           fast_tanh(p3.x), fast_tanh(p3.y));
                    *(float4*)&sA[(m0 + i) * 256 + (o0 ^ swzv)] = a;
                    *(float4*)&sA[(m0 + i) * 256 + ((o0 + 4) ^ swzv)] = b;
                }
            }
            float* nb = sW + ((ck + 1) & 1) * 4096;
            #pragma unroll
            for (int j = 0; j < 4; j++) {
                int k = j * 4;
                nb[(k + 0) * 256 + tid] = pf[j].x;
                nb[(k + 1) * 256 + tid] = pf[j].y;
                nb[(k + 2) * 256 + tid] = pf[j].z;
                nb[(k + 3) * 256 + tid] = pf[j].w;
            }
            __syncthreads();
        }
    }

    // ---- layer 2: 256 -> 256 (16 chunks of 16 k), tanh -> sA in place ----
    int ow = tid & 63;                 // W3 staging: output column
    int ks3 = (tid >> 6) * 8;          // W3 staging: k-slice within chunk
    const float* w3base = W3 + ((size_t)e * 64 + ow) * 256 + ks3;
    {
        ulonglong2 ba = *(const ulonglong2*)(B2 + (size_t)e * 256 + o0);
        ulonglong2 bb = *(const ulonglong2*)(B2 + (size_t)e * 256 + o0 + 4);
        #pragma unroll
        for (int i = 0; i < 4; i++) {
            acc[0][i] = ba.x; acc[1][i] = ba.y; acc[2][i] = bb.x; acc[3][i] = bb.y;
        }
        #pragma unroll 1
        for (int ck = 0; ck < 16; ck++) {
            if (ck < 15) {
                #pragma unroll
                for (int j = 0; j < 4; j++)
                    pf[j] = *(const float4*)(w2base + (ck + 1) * 16 + j * 4);
            } else {
                // prefetch W3 chunk 0 (k 0..32)
                pf[0] = *(const float4*)(w3base);
                pf[1] = *(const float4*)(w3base + 4);
            }

            gemm16<256>(sA + m0 * 256, sW + (ck & 1) * 4096 + o0, ck * 16, swzv, acc);

            if (ck < 15) {
                float* nb = sW + ((ck + 1) & 1) * 4096;
                #pragma unroll
                for (int j = 0; j < 4; j++) {
                    int k = j * 4;
                    nb[(k + 0) * 256 + tid] = pf[j].x;
                    nb[(k + 1) * 256 + tid] = pf[j].y;
                    nb[(k + 2) * 256 + tid] = pf[j].z;
                    nb[(k + 3) * 256 + tid] = pf[j].w;
                }
            } else {
                // store W3 chunk 0 -> buf0 as [k][64]
                float* nb = sW;        // buf0
                #pragma unroll
                for (int j = 0; j < 2; j++) {
                    float4 v = pf[j];
                    int k = ks3 + j * 4;
                    nb[(k + 0) * 64 + ow] = v.x;
                    nb[(k + 1) * 64 + ow] = v.y;
                    nb[(k + 2) * 64 + ow] = v.z;
                    nb[(k + 3) * 64 + ow] = v.w;
                }
            }
            __syncthreads();
        }
        // tanh -> h2 in place (all sA reads completed at the ck=15 barrier)
        #pragma unroll
        for (int i = 0; i < 4; i++) {
            float2 p0 = unpack2(acc[0][i]), p1 = unpack2(acc[1][i]);
            float2 p2 = unpack2(acc[2][i]), p3 = unpack2(acc[3][i]);
            float4 a = make_float4(fast_tanh(p0.x), fast_tanh(p0.y),
                                   fast_tanh(p1.x), fast_tanh(p1.y));
            float4 b = make_float4(fast_tanh(p2.x), fast_tanh(p2.y),
                                   fast_tanh(p3.x), fast_tanh(p3.y));
            *(float4*)&sA[(m0 + i) * 256 + (o0 ^ swzv)] = a;
            *(float4*)&sA[(m0 + i) * 256 + ((o0 + 4) ^ swzv)] = b;
        }
    }
    __syncthreads();

    // ---- layer 3: 256 -> 64 (8 chunks of 32 k), scatter to output ----
    {
        int o3 = (lane & 15) * 4;               // 4 outputs (2 pairs)
        int rg = wid * 2 + (lane >> 4);
        int m3 = rg * 2;                        // 2 rows
        int swz3 = ((m3 >> 2) & 7) * 4;

        ULL a3[2][2];
        ulonglong2 b3 = *(const ulonglong2*)(B3 + (size_t)e * 64 + o3);
        a3[0][0] = b3.x; a3[1][0] = b3.y;
        a3[0][1] = b3.x; a3[1][1] = b3.y;

        #pragma unroll 1
        for (int cz = 0; cz < 8; cz++) {
            float4 p3a, p3b;
            if (cz < 7) {
                p3a = *(const float4*)(w3base + (cz + 1) * 32);
                p3b = *(const float4*)(w3base + (cz + 1) * 32 + 4);
            }
            const float* wb = sW + (cz & 1) * 4096;
            #pragma unroll
            for (int q = 0; q < 8; q++) {
                int k4 = cz * 32 + q * 4;
                float4 xa = *(const float4*)&sA[m3 * 256 + (k4 ^ swz3)];
                float4 xb = *(const float4*)&sA[(m3 + 1) * 256 + (k4 ^ swz3)];
                #pragma unroll
                for (int kk = 0; kk < 4; kk++) {
                    ulonglong2 w = *(const ulonglong2*)&wb[(q * 4 + kk) * 64 + o3];
                    float v0 = (kk == 0) ? xa.x : (kk == 1) ? xa.y : (kk == 2) ? xa.z : xa.w;
                    float v1 = (kk == 0) ? xb.x : (kk == 1) ? xb.y : (kk == 2) ? xb.z : xb.w;
                    ULL d0 = dup2(v0), d1 = dup2(v1);
                    fma2(a3[0][0], d0, w.x);
                    fma2(a3[1][0], d0, w.y);
                    fma2(a3[0][1], d1, w.x);
                    fma2(a3[1][1], d1, w.y);
                }
            }
            if (cz < 7) {
                float* nb = sW + ((cz + 1) & 1) * 4096;
                int k = ks3;
                nb[(k + 0) * 64 + ow] = p3a.x;
                nb[(k + 1) * 64 + ow] = p3a.y;
                nb[(k + 2) * 64 + ow] = p3a.z;
                nb[(k + 3) * 64 + ow] = p3a.w;
                nb[(k + 4) * 64 + ow] = p3b.x;
                nb[(k + 5) * 64 + ow] = p3b.y;
                nb[(k + 6) * 64 + ow] = p3b.z;
                nb[(k + 7) * 64 + ow] = p3b.w;
                __syncthreads();
            }
        }
        #pragma unroll
        for (int im = 0; im < 2; im++) {
            int m = m3 + im;
            if (m < mrows) {
                int n = g_bucket[e * CAP + rs + m];
                float2 p0 = unpack2(a3[0][im]);
                float2 p1 = unpack2(a3[1][im]);
                float4 o = make_float4(p0.x, p0.y, p1.x, p1.y);
                *(float4*)&Og[(size_t)n * 64 + o3] = o;
            }
        }
    }
}

// ---------------- launch ----------------
extern "C" void kernel_launch(void* const* d_in, const int* in_sizes, int n_in,
                              void* d_out, int out_size) {
    const float* x  = (const float*)d_in[0];
    const int*   ind = (const int*)d_in[1];
    const float* W1 = (const float*)d_in[2];
    const float* b1 = (const float*)d_in[3];
    const float* W2 = (const float*)d_in[4];
    const float* b2 = (const float*)d_in[5];
    const float* Wl = (const float*)d_in[6];
    const float* bl = (const float*)d_in[7];
    float* out = (float*)d_out;

    (void)in_sizes; (void)n_in; (void)out_size;

    cudaFuncSetAttribute(k_mlp, cudaFuncAttributeMaxDynamicSharedMemorySize,
                         SMEM_FLOATS * (int)sizeof(float));

    void* cnt_ptr = nullptr;
    cudaGetSymbolAddress(&cnt_ptr, g_cnt);
    cudaMemsetAsync(cnt_ptr, 0, NEXP * sizeof(int));

    k_fill<<<N_ROWS / 256, 256>>>(ind);
    k_mlp<<<dim3(NEXP, TILES_Y), THREADS, SMEM_FLOATS * sizeof(float)>>>(
        x, W1, b1, W2, b2, Wl, bl, out);
}

// round 9
// speedup vs baseline: 1.5486x; 1.4915x over previous
#include <cuda_runtime.h>

// Problem constants
#define N_ROWS   16384
#define IN_DIM   64
#define NEXP     256
#define CAP      128     // per-expert bucket capacity (binomial max ~90, 8-sigma margin)
#define TM       32      // rows per tile
#define TILES_Y  4       // CAP / TM
#define THREADS  256

typedef unsigned long long ULL;

// ---------------- scratch ----------------
__device__ int g_cnt[NEXP];
__device__ int g_bucket[NEXP * CAP];

// ---------------- helpers ----------------
__device__ __forceinline__ void fma2(ULL &acc, ULL a, ULL b) {
    asm("fma.rn.f32x2 %0, %1, %2, %0;" : "+l"(acc) : "l"(a), "l"(b));
}
__device__ __forceinline__ ULL dup2(float x) {
    ULL r; asm("mov.b64 %0, {%1, %1};" : "=l"(r) : "f"(x)); return r;
}
__device__ __forceinline__ float2 unpack2(ULL v) {
    float2 r;
    r.x = __uint_as_float((unsigned)(v & 0xFFFFFFFFull));
    r.y = __uint_as_float((unsigned)(v >> 32));
    return r;
}
__device__ __forceinline__ float fast_tanh(float x) {
    float ax = fabsf(x);
    float t = __expf(-2.0f * ax);
    float r = __fdividef(1.0f - t, 1.0f + t);
    return copysignf(r, x);
}

// ---------------- grouping ----------------
__global__ void k_fill(const int* __restrict__ ind) {
    int i = blockIdx.x * blockDim.x + threadIdx.x;
    int e = ind[i];
    int p = atomicAdd(&g_cnt[e], 1);
    if (p < CAP) g_bucket[e * CAP + p] = i;
}

// ---------------- GEMM microkernel (32 k-steps) ----------------
// Thread tile: 8 outputs x 4 rows. xb pre-offset to row m0 (cols XOR-swizzled by swzv).
// wb: weight chunk [32][256], column-swizzled: W[o] at col o ^ ((kloc>>2 & 7)*4).
template <int LDX>
__device__ __forceinline__ void gemm32(const float* __restrict__ xb,
                                       const float* __restrict__ wb,
                                       int kx, int swzv, int o0, ULL acc[4][4]) {
    #pragma unroll
    for (int q = 0; q < 8; q++) {
        int xc = (kx + q * 4) ^ swzv;
        float4 xr[4];
        #pragma unroll
        for (int i = 0; i < 4; i++)
            xr[i] = *(const float4*)&xb[i * LDX + xc];
        int colA = o0 ^ ((q & 7) * 4);
        const float* wq = wb + q * 4 * 256;
        #pragma unroll
        for (int kk = 0; kk < 4; kk++) {
            ulonglong2 wlo = *(const ulonglong2*)&wq[kk * 256 + colA];
            ulonglong2 whi = *(const ulonglong2*)&wq[kk * 256 + (colA ^ 4)];
            #pragma unroll
            for (int i = 0; i < 4; i++) {
                float xv = (kk == 0) ? xr[i].x : (kk == 1) ? xr[i].y
                         : (kk == 2) ? xr[i].z : xr[i].w;
                ULL d = dup2(xv);
                fma2(acc[0][i], d, wlo.x);
                fma2(acc[1][i], d, wlo.y);
                fma2(acc[2][i], d, whi.x);
                fma2(acc[3][i], d, whi.y);
            }
        }
    }
}

// smem (floats): sA [32][256] (8192) | sX [32][64] (2048) | sW 2 x [32][256] (16384)
#define SMEM_FLOATS (8192 + 2048 + 16384)   // 26624 floats = 104 KB

__global__ __launch_bounds__(THREADS, 2)
void k_mlp(const float* __restrict__ Xg,
           const float* __restrict__ W1, const float* __restrict__ B1,
           const float* __restrict__ W2, const float* __restrict__ B2,
           const float* __restrict__ W3, const float* __restrict__ B3,
           float* __restrict__ Og) {
    int e = blockIdx.x;
    int cnt = min(g_cnt[e], CAP);
    int rs = (int)blockIdx.y * TM;
    if (rs >= cnt) return;
    int mrows = min(TM, cnt - rs);

    extern __shared__ float sm[];
    float* sA = sm;            // h1 then h2 (in place)
    float* sX = sm + 8192;     // x (swizzled)
    float* sW = sm + 10240;    // double buffer; also W3 halves [128][64]

    int tid = threadIdx.x;
    int lane = tid & 31, wid = tid >> 5;
    int c = lane & 7, r = lane >> 3;
    int cb = wid & 3, rb = wid >> 2;
    int o0 = cb * 64 + c * 8;            // 8 outputs
    int m0 = rb * 16 + r * 4;            // 4 rows
    int swzv = ((m0 >> 2) & 7) * 4;
    bool tact = (m0 < mrows);

    // ---- stage x into sX[m][64], cols XOR-swizzled, zero-pad ----
    {
        int mx = tid >> 3, px = tid & 7;
        float4 v0, v1;
        if (mx < mrows) {
            int n = g_bucket[e * CAP + rs + mx];
            const float4* src = (const float4*)(Xg + (size_t)n * IN_DIM) + px * 2;
            v0 = src[0]; v1 = src[1];
        } else {
            v0 = make_float4(0.f, 0.f, 0.f, 0.f); v1 = v0;
        }
        int sx = ((mx >> 2) & 7) * 4;
        *(float4*)&sX[mx * 64 + ((px * 8) ^ sx)] = v0;
        *(float4*)&sX[mx * 64 + ((px * 8 + 4) ^ sx)] = v1;
    }

    // ---- coalesced weight-loader lanes: row lo, k-offset lk ----
    int lo = tid >> 3;              // 0..31
    int lk = (tid & 7) * 4;         // 0..28
    int sbase = lo ^ lk;            // swizzled sts column base (+32p)
    const float* w1row = W1 + ((size_t)e * 256 + lo) * 64 + lk;
    const float* w2row = W2 + ((size_t)e * 256 + lo) * 256 + lk;
    const float* w3row = W3 + ((size_t)e * 64 + lo) * 256 + lk;

    float4 pf[8];

    // ---- W1 chunk 0 -> buf0 (coalesced: 4 full lines per LDG) ----
    #pragma unroll
    for (int p = 0; p < 8; p++) pf[p] = *(const float4*)(w1row + p * 32 * 64);
    #pragma unroll
    for (int p = 0; p < 8; p++) {
        int col = sbase + 32 * p;
        sW[(lk + 0) * 256 + col] = pf[p].x;
        sW[(lk + 1) * 256 + col] = pf[p].y;
        sW[(lk + 2) * 256 + col] = pf[p].z;
        sW[(lk + 3) * 256 + col] = pf[p].w;
    }
    __syncthreads();

    ULL acc[4][4];

    // ---- layer 1: 64 -> 256, two 32-k chunks ----
    {
        ulonglong2 ba = *(const ulonglong2*)(B1 + (size_t)e * 256 + o0);
        ulonglong2 bb = *(const ulonglong2*)(B1 + (size_t)e * 256 + o0 + 4);
        #pragma unroll
        for (int i = 0; i < 4; i++) {
            acc[0][i] = ba.x; acc[1][i] = ba.y; acc[2][i] = bb.x; acc[3][i] = bb.y;
        }
        // chunk 0 (prefetch W1 chunk 1)
        #pragma unroll
        for (int p = 0; p < 8; p++) pf[p] = *(const float4*)(w1row + 32 + p * 32 * 64);
        if (tact) gemm32<64>(sX + m0 * 64, sW, 0, swzv, o0, acc);
        {
            float* nb = sW + 8192;
            #pragma unroll
            for (int p = 0; p < 8; p++) {
                int col = sbase + 32 * p;
                nb[(lk + 0) * 256 + col] = pf[p].x;
                nb[(lk + 1) * 256 + col] = pf[p].y;
                nb[(lk + 2) * 256 + col] = pf[p].z;
                nb[(lk + 3) * 256 + col] = pf[p].w;
            }
        }
        __syncthreads();
        // chunk 1 (prefetch W2 chunk 0)
        #pragma unroll
        for (int p = 0; p < 8; p++) pf[p] = *(const float4*)(w2row + p * 32 * 256);
        if (tact) gemm32<64>(sX + m0 * 64, sW + 8192, 32, swzv, o0, acc);
        if (tact) {
            #pragma unroll
            for (int i = 0; i < 4; i++) {
                float2 p0 = unpack2(acc[0][i]), p1 = unpack2(acc[1][i]);
                float2 p2 = unpack2(acc[2][i]), p3 = unpack2(acc[3][i]);
                float4 a = make_float4(fast_tanh(p0.x), fast_tanh(p0.y),
                                       fast_tanh(p1.x), fast_tanh(p1.y));
                float4 b = make_float4(fast_tanh(p2.x), fast_tanh(p2.y),
                                       fast_tanh(p3.x), fast_tanh(p3.y));
                int base = (m0 + i) * 256;
                *(float4*)&sA[base + (o0 ^ swzv)] = a;
                *(float4*)&sA[base + ((o0 + 4) ^ swzv)] = b;
            }
        }
        {   // sts W2 chunk 0 -> buf0 (buf0 reads done at prior barrier)
            #pragma unroll
            for (int p = 0; p < 8; p++) {
                int col = sbase + 32 * p;
                sW[(lk + 0) * 256 + col] = pf[p].x;
                sW[(lk + 1) * 256 + col] = pf[p].y;
                sW[(lk + 2) * 256 + col] = pf[p].z;
                sW[(lk + 3) * 256 + col] = pf[p].w;
            }
        }
        __syncthreads();
    }

    // ---- layer 2: 256 -> 256, 8 pipelined 32-k chunks ----
    {
        ulonglong2 ba = *(const ulonglong2*)(B2 + (size_t)e * 256 + o0);
        ulonglong2 bb = *(const ulonglong2*)(B2 + (size_t)e * 256 + o0 + 4);
        #pragma unroll
        for (int i = 0; i < 4; i++) {
            acc[0][i] = ba.x; acc[1][i] = ba.y; acc[2][i] = bb.x; acc[3][i] = bb.y;
        }
        #pragma unroll 1
        for (int ck = 0; ck < 8; ck++) {
            if (ck < 7) {
                #pragma unroll
                for (int p = 0; p < 8; p++)
                    pf[p] = *(const float4*)(w2row + (ck + 1) * 32 + p * 32 * 256);
            } else {
                // prefetch W3 lower half (k 0..128), coalesced
                #pragma unroll
                for (int p = 0; p < 2; p++)
                    #pragma unroll
                    for (int j = 0; j < 4; j++)
                        pf[p * 4 + j] = *(const float4*)(w3row + p * 32 * 256 + j * 32);
            }

            if (tact) gemm32<256>(sA + m0 * 256, sW + (ck & 1) * 8192, ck * 32, swzv, o0, acc);

            if (ck < 7) {
                float* nb = sW + ((ck + 1) & 1) * 8192;
                #pragma unroll
                for (int p = 0; p < 8; p++) {
                    int col = sbase + 32 * p;
                    nb[(lk + 0) * 256 + col] = pf[p].x;
                    nb[(lk + 1) * 256 + col] = pf[p].y;
                    nb[(lk + 2) * 256 + col] = pf[p].z;
                    nb[(lk + 3) * 256 + col] = pf[p].w;
                }
            } else {
                // sts W3 lower half -> buf0 as [128][64], swizzled
                #pragma unroll
                for (int p = 0; p < 2; p++) {
                    #pragma unroll
                    for (int j = 0; j < 4; j++) {
                        int kb = lk + j * 32;
                        int col = (lo + 32 * p) ^ ((((tid & 7) + 8 * j) & 15) * 4);
                        float4 v = pf[p * 4 + j];
                        sW[(kb + 0) * 64 + col] = v.x;
                        sW[(kb + 1) * 64 + col] = v.y;
                        sW[(kb + 2) * 64 + col] = v.z;
                        sW[(kb + 3) * 64 + col] = v.w;
                    }
                }
            }
            __syncthreads();
        }
        // tanh -> h2 in place
        if (tact) {
            #pragma unroll
            for (int i = 0; i < 4; i++) {
                float2 p0 = unpack2(acc[0][i]), p1 = unpack2(acc[1][i]);
                float2 p2 = unpack2(acc[2][i]), p3 = unpack2(acc[3][i]);
                float4 a = make_float4(fast_tanh(p0.x), fast_tanh(p0.y),
                                       fast_tanh(p1.x), fast_tanh(p1.y));
                float4 b = make_float4(fast_tanh(p2.x), fast_tanh(p2.y),
                                       fast_tanh(p3.x), fast_tanh(p3.y));
                int base = (m0 + i) * 256;
                *(float4*)&sA[base + (o0 ^ swzv)] = a;
                *(float4*)&sA[base + ((o0 + 4) ^ swzv)] = b;
            }
        }
        __syncthreads();
    }

    // ---- layer 3: 256 -> 64, two 128-k halves, scatter ----
    {
        int o3 = (lane & 15) * 4;             // 4 outputs
        int m3 = wid * 4 + (lane >> 4) * 2;   // 2 rows
        int swzm = ((m3 >> 2) & 7) * 4;

        ULL a3[2][2];
        ulonglong2 b3 = *(const ulonglong2*)(B3 + (size_t)e * 64 + o3);
        a3[0][0] = b3.x; a3[1][0] = b3.y;
        a3[0][1] = b3.x; a3[1][1] = b3.y;

        // prefetch W3 upper half
        #pragma unroll
        for (int p = 0; p < 2; p++)
            #pragma unroll
            for (int j = 0; j < 4; j++)
                pf[p * 4 + j] = *(const float4*)(w3row + 128 + p * 32 * 256 + j * 32);

        #pragma unroll 1
        for (int h = 0; h < 2; h++) {
            const float* wb = sW + h * 8192;
            #pragma unroll 4
            for (int q = 0; q < 32; q++) {
                int kg = h * 128 + q * 4;
                float4 xa = *(const float4*)&sA[m3 * 256 + (kg ^ swzm)];
                float4 xc = *(const float4*)&sA[(m3 + 1) * 256 + (kg ^ swzm)];
                int col = o3 ^ ((q & 15) * 4);
                #pragma unroll
                for (int kk = 0; kk < 4; kk++) {
                    ulonglong2 w = *(const ulonglong2*)&wb[(q * 4 + kk) * 64 + col];
                    float v0 = (kk == 0) ? xa.x : (kk == 1) ? xa.y : (kk == 2) ? xa.z : xa.w;
                    float v1 = (kk == 0) ? xc.x : (kk == 1) ? xc.y : (kk == 2) ? xc.z : xc.w;
                    ULL d0 = dup2(v0), d1 = dup2(v1);
                    fma2(a3[0][0], d0, w.x);
                    fma2(a3[1][0], d0, w.y);
                    fma2(a3[0][1], d1, w.x);
                    fma2(a3[1][1], d1, w.y);
                }
            }
            if (h == 0) {
                // sts W3 upper half -> buf1 (free since post-epilogue barrier)
                float* nb = sW + 8192;
                #pragma unroll
                for (int p = 0; p < 2; p++) {
                    #pragma unroll
                    for (int j = 0; j < 4; j++) {
                        int kb = lk + j * 32;
                        int col = (lo + 32 * p) ^ ((((tid & 7) + 8 * j) & 15) * 4);
                        float4 v = pf[p * 4 + j];
                        nb[(kb + 0) * 64 + col] = v.x;
                        nb[(kb + 1) * 64 + col] = v.y;
                        nb[(kb + 2) * 64 + col] = v.z;
                        nb[(kb + 3) * 64 + col] = v.w;
                    }
                }
                __syncthreads();
            }
        }
        #pragma unroll
        for (int im = 0; im < 2; im++) {
            int m = m3 + im;
            if (m < mrows) {
                int n = g_bucket[e * CAP + rs + m];
                float2 q0 = unpack2(a3[0][im]);
                float2 q1 = unpack2(a3[1][im]);
                *(float4*)&Og[(size_t)n * 64 + o3] = make_float4(q0.x, q0.y, q1.x, q1.y);
            }
        }
    }
}

// ---------------- launch ----------------
extern "C" void kernel_launch(void* const* d_in, const int* in_sizes, int n_in,
                              void* d_out, int out_size) {
    const float* x  = (const float*)d_in[0];
    const int*   ind = (const int*)d_in[1];
    const float* W1 = (const float*)d_in[2];
    const float* b1 = (const float*)d_in[3];
    const float* W2 = (const float*)d_in[4];
    const float* b2 = (const float*)d_in[5];
    const float* Wl = (const float*)d_in[6];
    const float* bl = (const float*)d_in[7];
    float* out = (float*)d_out;

    (void)in_sizes; (void)n_in; (void)out_size;

    cudaFuncSetAttribute(k_mlp, cudaFuncAttributeMaxDynamicSharedMemorySize,
                         SMEM_FLOATS * (int)sizeof(float));

    void* cnt_ptr = nullptr;
    cudaGetSymbolAddress(&cnt_ptr, g_cnt);
    cudaMemsetAsync(cnt_ptr, 0, NEXP * sizeof(int));

    k_fill<<<N_ROWS / 256, 256>>>(ind);
    k_mlp<<<dim3(NEXP, TILES_Y), THREADS, SMEM_FLOATS * sizeof(float)>>>(
        x, W1, b1, W2, b2, Wl, bl, out);
}

// round 13
// speedup vs baseline: 2.5237x; 1.6297x over previous
#include <cuda_runtime.h>
#include <cuda_bf16.h>
#include <cstdint>

#define NEXP    256
#define CAP     128
#define N_ROWS  16384
#define THREADS 512

// smem byte offsets
#define HHI   0         // h hi  [128][256] bf16, stride 512B
#define HLO   65536     // h lo
#define WBUF  131072    // 64KB: 2 chunk bufs (hi 16K + lo 16K each); also W3 (hi 32K @WBUF, lo 32K @+32768)
#define XHI   196608    // x hi [128][64] bf16, stride 128B
#define XLO   212992
#define SMEM_TOTAL 229376

__device__ int g_cnt[NEXP];
__device__ int g_bucket[NEXP * CAP];

// ---------------- grouping ----------------
__global__ void k_fill(const int* __restrict__ ind) {
    int i = blockIdx.x * blockDim.x + threadIdx.x;
    int e = ind[i];
    int p = atomicAdd(&g_cnt[e], 1);
    if (p < CAP) g_bucket[e * CAP + p] = i;
}

// ---------------- helpers ----------------
__device__ __forceinline__ uint32_t smem_u32(const void* p) {
    uint32_t a;
    asm("{ .reg .u64 t; cvta.to.shared.u64 t, %1; cvt.u32.u64 %0, t; }" : "=r"(a) : "l"(p));
    return a;
}
__device__ __forceinline__ void ldm4(uint32_t* r, uint32_t a) {
    asm volatile("ldmatrix.sync.aligned.m8n8.x4.shared.b16 {%0,%1,%2,%3}, [%4];"
        : "=r"(r[0]), "=r"(r[1]), "=r"(r[2]), "=r"(r[3]) : "r"(a));
}
__device__ __forceinline__ void mma16816(float* d, const uint32_t* a, const uint32_t* b) {
    asm volatile("mma.sync.aligned.m16n8k16.row.col.f32.bf16.bf16.f32 "
        "{%0,%1,%2,%3}, {%4,%5,%6,%7}, {%8,%9}, {%0,%1,%2,%3};"
        : "+f"(d[0]), "+f"(d[1]), "+f"(d[2]), "+f"(d[3])
        : "r"(a[0]), "r"(a[1]), "r"(a[2]), "r"(a[3]), "r"(b[0]), "r"(b[1]));
}
__device__ __forceinline__ float fast_tanh(float x) {
    float ax = fabsf(x);
    float t = __expf(-2.0f * ax);
    float r = __fdividef(1.0f - t, 1.0f + t);
    return copysignf(r, x);
}
__device__ __forceinline__ uint32_t bpackr(float x, float y, float& rx, float& ry) {
    __nv_bfloat16 hx = __float2bfloat16_rn(x), hy = __float2bfloat16_rn(y);
    rx = x - __bfloat162float(hx);
    ry = y - __bfloat162float(hy);
    return (uint32_t)__bfloat16_as_ushort(hx) | ((uint32_t)__bfloat16_as_ushort(hy) << 16);
}
__device__ __forceinline__ uint32_t bpack(float x, float y) {
    return (uint32_t)__bfloat16_as_ushort(__float2bfloat16_rn(x)) |
           ((uint32_t)__bfloat16_as_ushort(__float2bfloat16_rn(y)) << 16);
}
__device__ __forceinline__ void split8(float4 a, float4 b, uint4& hi, uint4& lo) {
    float r0, r1, r2, r3, r4, r5, r6, r7;
    hi.x = bpackr(a.x, a.y, r0, r1);
    hi.y = bpackr(a.z, a.w, r2, r3);
    hi.z = bpackr(b.x, b.y, r4, r5);
    hi.w = bpackr(b.z, b.w, r6, r7);
    lo.x = bpack(r0, r1); lo.y = bpack(r2, r3);
    lo.z = bpack(r4, r5); lo.w = bpack(r6, r7);
}

// swizzled byte offsets (all verified conflict-free for ldmatrix & STS patterns)
__device__ __forceinline__ uint32_t aoff(int m, int kb)  { return m * 512 + (kb ^ ((m & 7) << 4)); }
__device__ __forceinline__ uint32_t xoff(int m, int kb)  { return m * 128 + (kb ^ ((m & 7) << 4)); }
__device__ __forceinline__ uint32_t woff(int o, int kb)  { return o * 64  + (kb ^ (((o >> 1) & 3) << 4)); }
__device__ __forceinline__ uint32_t woff3(int o, int kb) { return o * 512 + (kb ^ ((o & 7) << 4)); }

extern __shared__ char smc[];

// store one 16-float weight slice (hi/lo split) into a chunk buffer [256 o][32 k]
__device__ __forceinline__ void sts_chunk(uint32_t bufOff, int o, int khB, const float4* pf) {
    uint4 h0, h1, l0, l1;
    split8(pf[0], pf[1], h0, l0);
    split8(pf[2], pf[3], h1, l1);
    *(uint4*)(smc + bufOff + woff(o, khB))           = h0;
    *(uint4*)(smc + bufOff + woff(o, khB + 16))      = h1;
    *(uint4*)(smc + bufOff + 16384 + woff(o, khB))      = l0;
    *(uint4*)(smc + bufOff + 16384 + woff(o, khB + 16)) = l1;
}

__global__ __launch_bounds__(THREADS, 1)
void k_mlp(const float* __restrict__ Xg,
           const float* __restrict__ W1, const float* __restrict__ B1,
           const float* __restrict__ W2, const float* __restrict__ B2,
           const float* __restrict__ W3, const float* __restrict__ B3,
           float* __restrict__ Og) {
    int e = blockIdx.x;
    int mrows = min(g_cnt[e], CAP);
    if (mrows == 0) return;

    int tid = threadIdx.x;
    int lane = tid & 31, wid = tid >> 5;
    int rg = wid >> 1, ch = wid & 1;
    int m0 = rg * 16;
    bool act = (m0 < mrows);
    uint32_t sb = smem_u32(smc);

    // ldmatrix lane address components
    int aRow = lane & 15;
    int aK = (lane >> 4) << 4;                       // byte addend
    int bO = (lane & 7) | ((lane >> 4) << 3);
    int bK = ((lane >> 3) & 1) << 4;                 // byte addend

    // ---- stage x (hi/lo, swizzled), zero-pad ----
    {
        int m = tid >> 2, kq = (tid & 3) * 16;
        float4 v[4];
        if (m < mrows) {
            int n = g_bucket[e * CAP + m];
            const float4* src = (const float4*)(Xg + (size_t)n * 64 + kq);
            #pragma unroll
            for (int j = 0; j < 4; j++) v[j] = src[j];
        } else {
            #pragma unroll
            for (int j = 0; j < 4; j++) v[j] = make_float4(0.f, 0.f, 0.f, 0.f);
        }
        uint4 h0, h1, l0, l1;
        split8(v[0], v[1], h0, l0);
        split8(v[2], v[3], h1, l1);
        int kb = kq * 2;
        *(uint4*)(smc + XHI + xoff(m, kb))      = h0;
        *(uint4*)(smc + XHI + xoff(m, kb + 16)) = h1;
        *(uint4*)(smc + XLO + xoff(m, kb))      = l0;
        *(uint4*)(smc + XLO + xoff(m, kb + 16)) = l1;
    }
    // ---- stage W1: chunk0 -> buf0, chunk1 -> buf1 ----
    int so = tid >> 1;                   // staging o row (0..255)
    int skh = (tid & 1) * 16;            // staging k offset (elements)
    int skhB = skh * 2;                  // bytes
    {
        #pragma unroll
        for (int c = 0; c < 2; c++) {
            const float* src = W1 + (size_t)e * 16384 + so * 64 + c * 32 + skh;
            float4 v[4];
            #pragma unroll
            for (int j = 0; j < 4; j++) v[j] = *(const float4*)(src + j * 4);
            sts_chunk(WBUF + c * 32768, so, skhB, v);
        }
    }
    __syncthreads();

    float acc[64];
    #pragma unroll
    for (int i = 0; i < 64; i++) acc[i] = 0.f;

    // ---- layer 1: 64 -> 256 ----
    if (act) {
        #pragma unroll
        for (int kb4 = 0; kb4 < 4; kb4++) {
            int k0 = kb4 * 16;
            uint32_t aaddr = sb + XHI + xoff(m0 + aRow, k0 * 2 + aK);
            uint32_t ah[4], al[4];
            ldm4(ah, aaddr);
            ldm4(al, aaddr + (XLO - XHI));
            uint32_t bufH = sb + WBUF + (kb4 >> 1) * 32768;
            #pragma unroll
            for (int np = 0; np < 8; np++) {
                int n0 = ch * 128 + np * 16;
                uint32_t baddr = bufH + woff(n0 + bO, (kb4 & 1) * 32 + bK);
                uint32_t bh[4], bl[4];
                ldm4(bh, baddr);
                ldm4(bl, baddr + 16384);
                float* A0 = acc + np * 8;
                mma16816(A0, ah, bh);
                mma16816(A0, ah, bl);
                mma16816(A0, al, bh);
                mma16816(A0 + 4, ah, bh + 2);
                mma16816(A0 + 4, ah, bl + 2);
                mma16816(A0 + 4, al, bh + 2);
            }
        }
    }

    // prefetch W2 chunk 0
    const float* w2t = W2 + (size_t)e * 65536 + so * 256 + skh;
    float4 pf[4];
    #pragma unroll
    for (int j = 0; j < 4; j++) pf[j] = *(const float4*)(w2t + j * 4);

    // epilogue 1: + bias, tanh, split -> h
    if (act) {
        const float* bg = B1 + (size_t)e * 256;
        int r0 = m0 + (lane >> 2);
        #pragma unroll
        for (int t = 0; t < 16; t++) {
            int c0 = ch * 128 + t * 8 + (lane & 3) * 2;
            float2 bv = *(const float2*)(bg + c0);
            float v0 = fast_tanh(acc[t * 4 + 0] + bv.x);
            float v1 = fast_tanh(acc[t * 4 + 1] + bv.y);
            float v2 = fast_tanh(acc[t * 4 + 2] + bv.x);
            float v3 = fast_tanh(acc[t * 4 + 3] + bv.y);
            float q0, q1, q2, q3;
            uint32_t h0 = bpackr(v0, v1, q0, q1), l0v = bpack(q0, q1);
            uint32_t h1 = bpackr(v2, v3, q2, q3), l1v = bpack(q2, q3);
            int kb = c0 * 2;
            *(uint32_t*)(smc + HHI + aoff(r0, kb))     = h0;
            *(uint32_t*)(smc + HLO + aoff(r0, kb))     = l0v;
            *(uint32_t*)(smc + HHI + aoff(r0 + 8, kb)) = h1;
            *(uint32_t*)(smc + HLO + aoff(r0 + 8, kb)) = l1v;
        }
    }
    __syncthreads();           // all L1 mma reads of bufs done
    sts_chunk(WBUF, so, skhB, pf);
    __syncthreads();

    #pragma unroll
    for (int i = 0; i < 64; i++) acc[i] = 0.f;

    // ---- layer 2: 256 -> 256, 8 pipelined 32-k chunks ----
    #pragma unroll 1
    for (int c = 0; c < 8; c++) {
        if (c < 7) {
            #pragma unroll
            for (int j = 0; j < 4; j++) pf[j] = *(const float4*)(w2t + (c + 1) * 32 + j * 4);
        }
        if (act) {
            uint32_t bufH = sb + WBUF + (c & 1) * 32768;
            #pragma unroll
            for (int kk = 0; kk < 2; kk++) {
                int k0 = c * 32 + kk * 16;
                uint32_t aaddr = sb + HHI + aoff(m0 + aRow, k0 * 2 + aK);
                uint32_t ah[4], al[4];
                ldm4(ah, aaddr);
                ldm4(al, aaddr + 65536);
                #pragma unroll
                for (int np = 0; np < 8; np++) {
                    int n0 = ch * 128 + np * 16;
                    uint32_t baddr = bufH + woff(n0 + bO, kk * 32 + bK);
                    uint32_t bh[4], bl[4];
                    ldm4(bh, baddr);
                    ldm4(bl, baddr + 16384);
                    float* A0 = acc + np * 8;
                    mma16816(A0, ah, bh);
                    mma16816(A0, ah, bl);
                    mma16816(A0, al, bh);
                    mma16816(A0 + 4, ah, bh + 2);
                    mma16816(A0 + 4, ah, bl + 2);
                    mma16816(A0 + 4, al, bh + 2);
                }
            }
        }
        if (c < 7) sts_chunk(WBUF + ((c + 1) & 1) * 32768, so, skhB, pf);
        __syncthreads();
    }

    // ---- W3 LDG + epilogue 2 (overlapped) ----
    int o3 = tid >> 3, kq3 = (tid & 7) * 32;
    const float* w3t = W3 + (size_t)e * 16384 + o3 * 256 + kq3;
    float4 p3[8];
    #pragma unroll
    for (int j = 0; j < 8; j++) p3[j] = *(const float4*)(w3t + j * 4);

    if (act) {
        const float* bg = B2 + (size_t)e * 256;
        int r0 = m0 + (lane >> 2);
        #pragma unroll
        for (int t = 0; t < 16; t++) {
            int c0 = ch * 128 + t * 8 + (lane & 3) * 2;
            float2 bv = *(const float2*)(bg + c0);
            float v0 = fast_tanh(acc[t * 4 + 0] + bv.x);
            float v1 = fast_tanh(acc[t * 4 + 1] + bv.y);
            float v2 = fast_tanh(acc[t * 4 + 2] + bv.x);
            float v3 = fast_tanh(acc[t * 4 + 3] + bv.y);
            float q0, q1, q2, q3;
            uint32_t h0 = bpackr(v0, v1, q0, q1), l0v = bpack(q0, q1);
            uint32_t h1 = bpackr(v2, v3, q2, q3), l1v = bpack(q2, q3);
            int kb = c0 * 2;
            *(uint32_t*)(smc + HHI + aoff(r0, kb))     = h0;
            *(uint32_t*)(smc + HLO + aoff(r0, kb))     = l0v;
            *(uint32_t*)(smc + HHI + aoff(r0 + 8, kb)) = h1;
            *(uint32_t*)(smc + HLO + aoff(r0 + 8, kb)) = l1v;
        }
    }
    // stage W3 -> WBUF region ([64][256], hi @WBUF, lo @+32768)
    {
        #pragma unroll
        for (int j = 0; j < 4; j++) {
            uint4 hi, lo;
            split8(p3[2 * j], p3[2 * j + 1], hi, lo);
            uint32_t kb = kq3 * 2 + j * 16;
            *(uint4*)(smc + WBUF + woff3(o3, kb))         = hi;
            *(uint4*)(smc + WBUF + 32768 + woff3(o3, kb)) = lo;
        }
    }
    __syncthreads();

    // ---- layer 3: 256 -> 64 ----
    float acc3[16];
    #pragma unroll
    for (int i = 0; i < 16; i++) acc3[i] = 0.f;
    if (act) {
        #pragma unroll 4
        for (int kb16 = 0; kb16 < 16; kb16++) {
            int k0 = kb16 * 16;
            uint32_t aaddr = sb + HHI + aoff(m0 + aRow, k0 * 2 + aK);
            uint32_t ah[4], al[4];
            ldm4(ah, aaddr);
            ldm4(al, aaddr + 65536);
            #pragma unroll
            for (int np = 0; np < 2; np++) {
                int n0 = ch * 32 + np * 16;
                uint32_t baddr = sb + WBUF + woff3(n0 + bO, k0 * 2 + bK);
                uint32_t bh[4], bl[4];
                ldm4(bh, baddr);
                ldm4(bl, baddr + 32768);
                float* A0 = acc3 + np * 8;
                mma16816(A0, ah, bh);
                mma16816(A0, ah, bl);
                mma16816(A0, al, bh);
                mma16816(A0 + 4, ah, bh + 2);
                mma16816(A0 + 4, ah, bl + 2);
                mma16816(A0 + 4, al, bh + 2);
            }
        }
        // epilogue 3: + bias -> scatter
        const float* bg = B3 + (size_t)e * 64;
        int r0 = m0 + (lane >> 2), r1 = r0 + 8;
        int n0g = (r0 < mrows) ? g_bucket[e * CAP + r0] : -1;
        int n1g = (r1 < mrows) ? g_bucket[e * CAP + r1] : -1;
        #pragma unroll
        for (int t = 0; t < 4; t++) {
            int c0 = ch * 32 + t * 8 + (lane & 3) * 2;
            float2 bv = *(const float2*)(bg + c0);
            if (n0g >= 0) {
                float2 o = make_float2(acc3[t * 4 + 0] + bv.x, acc3[t * 4 + 1] + bv.y);
                *(float2*)(Og + (size_t)n0g * 64 + c0) = o;
            }
            if (n1g >= 0) {
                float2 o = make_float2(acc3[t * 4 + 2] + bv.x, acc3[t * 4 + 3] + bv.y);
                *(float2*)(Og + (size_t)n1g * 64 + c0) = o;
            }
        }
    }
}

// ---------------- launch ----------------
extern "C" void kernel_launch(void* const* d_in, const int* in_sizes, int n_in,
                              void* d_out, int out_size) {
    const float* x  = (const float*)d_in[0];
    const int*   ind = (const int*)d_in[1];
    const float* W1 = (const float*)d_in[2];
    const float* b1 = (const float*)d_in[3];
    const float* W2 = (const float*)d_in[4];
    const float* b2 = (const float*)d_in[5];
    const float* Wl = (const float*)d_in[6];
    const float* bl = (const float*)d_in[7];
    float* out = (float*)d_out;

    (void)in_sizes; (void)n_in; (void)out_size;

    cudaFuncSetAttribute(k_mlp, cudaFuncAttributeMaxDynamicSharedMemorySize, SMEM_TOTAL);

    void* cnt_ptr = nullptr;
    cudaGetSymbolAddress(&cnt_ptr, g_cnt);
    cudaMemsetAsync(cnt_ptr, 0, NEXP * sizeof(int));

    k_fill<<<N_ROWS / 256, 256>>>(ind);
    k_mlp<<<NEXP, THREADS, SMEM_TOTAL>>>(x, W1, b1, W2, b2, Wl, bl, out);
}